// round 5
// baseline (speedup 1.0000x reference)
#include <cuda_runtime.h>
#include <math.h>

#define BSZ 32
#define SEQ 512
#define IDIM 512
#define HDIM 512
#define G4H 2048

#define OUT_HT_ELEMS (BSZ*SEQ*2*HDIM)              // 16777216
#define OUT_HN_OFF   OUT_HT_ELEMS
#define OUT_CN_OFF   (OUT_HT_ELEMS + 2*BSZ*HDIM)   // 16809984
#define OUT_TOTAL    (OUT_CN_OFF + 2*BSZ*HDIM)     // 16842752

// Scratch (allocation-free rule: __device__ globals)
__device__ float    g_G[2][SEQ][BSZ][G4H];   // precomputed x@Wih^T + bias, 256MB
__device__ float    g_h[2][2][BSZ][HDIM];    // [buf][dir][b][k] double-buffered h
__device__ unsigned g_cnt[2][2];             // [dir][grp] arrival counters
__device__ unsigned g_gen[2][2];             // [dir][grp] monotonic generation

__device__ __forceinline__ void fma2(unsigned long long& acc,
                                     unsigned long long a, unsigned long long b) {
    asm("fma.rn.f32x2 %0, %1, %2, %0;" : "+l"(acc) : "l"(a), "l"(b));
}
__device__ __forceinline__ float red2(unsigned long long v) {
    float lo, hi;
    asm("mov.b64 {%0, %1}, %2;" : "=f"(lo), "=f"(hi) : "l"(v));
    return lo + hi;
}
__device__ __forceinline__ unsigned long long dup2(float x) {
    unsigned long long r;
    asm("mov.b64 %0, {%1, %1};" : "=l"(r) : "f"(x));
    return r;
}
__device__ __forceinline__ float2 upk2(unsigned long long v) {
    float2 r;
    asm("mov.b64 {%0, %1}, %2;" : "=f"(r.x), "=f"(r.y) : "l"(v));
    return r;
}
__device__ __forceinline__ float sigm(float x) { return 1.0f / (1.0f + expf(-x)); }

// ---------------------------------------------------------------------------
// Kernel 1: input-projection GEMM with packed f32x2 FMAs (unchanged from R4).
// ---------------------------------------------------------------------------
__global__ void __launch_bounds__(256) ih_gemm_kernel(
    const float* __restrict__ X,
    const float* __restrict__ Wih_f, const float* __restrict__ bih_f, const float* __restrict__ bhh_f,
    const float* __restrict__ Wih_b, const float* __restrict__ bih_b, const float* __restrict__ bhh_b)
{
    __shared__ float Xs[16][68];
    __shared__ float Ws[16][68];

    const int dir = blockIdx.z;
    const float* __restrict__ W   = dir ? Wih_b : Wih_f;
    const float* __restrict__ bih = dir ? bih_b : bih_f;
    const float* __restrict__ bhh = dir ? bhh_b : bhh_f;

    const int tid = threadIdx.x;
    const int tx = tid & 15;
    const int ty = tid >> 4;
    const int n0 = blockIdx.x * 64;
    const int m0 = blockIdx.y * 64;
    const int lrow = tid >> 2;
    const int lkq  = (tid & 3) * 4;

    unsigned long long acc2[4][2];
    #pragma unroll
    for (int i = 0; i < 4; i++) { acc2[i][0] = 0ull; acc2[i][1] = 0ull; }

    const float* Xp = X + (size_t)(m0 + lrow) * IDIM + lkq;
    const float* Wp = W + (size_t)(n0 + lrow) * IDIM + lkq;

    for (int k0 = 0; k0 < IDIM; k0 += 16) {
        float4 xv = *(const float4*)(Xp + k0);
        float4 wv = *(const float4*)(Wp + k0);
        Xs[lkq + 0][lrow] = xv.x; Xs[lkq + 1][lrow] = xv.y;
        Xs[lkq + 2][lrow] = xv.z; Xs[lkq + 3][lrow] = xv.w;
        Ws[lkq + 0][lrow] = wv.x; Ws[lkq + 1][lrow] = wv.y;
        Ws[lkq + 2][lrow] = wv.z; Ws[lkq + 3][lrow] = wv.w;
        __syncthreads();
        #pragma unroll
        for (int kk = 0; kk < 16; kk++) {
            float4 av = *(const float4*)&Xs[kk][ty * 4];
            ulonglong2 bp = *(const ulonglong2*)&Ws[kk][tx * 4];
            unsigned long long d0 = dup2(av.x);
            unsigned long long d1 = dup2(av.y);
            unsigned long long d2 = dup2(av.z);
            unsigned long long d3 = dup2(av.w);
            fma2(acc2[0][0], d0, bp.x); fma2(acc2[0][1], d0, bp.y);
            fma2(acc2[1][0], d1, bp.x); fma2(acc2[1][1], d1, bp.y);
            fma2(acc2[2][0], d2, bp.x); fma2(acc2[2][1], d2, bp.y);
            fma2(acc2[3][0], d3, bp.x); fma2(acc2[3][1], d3, bp.y);
        }
        __syncthreads();
    }

    const int n = n0 + tx * 4;
    float4 bias4;
    bias4.x = bih[n + 0] + bhh[n + 0];
    bias4.y = bih[n + 1] + bhh[n + 1];
    bias4.z = bih[n + 2] + bhh[n + 2];
    bias4.w = bih[n + 3] + bhh[n + 3];

    float* Gout = &g_G[dir][0][0][0];
    #pragma unroll
    for (int mi = 0; mi < 4; mi++) {
        int m = m0 + ty * 4 + mi;
        int b = m >> 9;
        int t = m & 511;
        float2 u0 = upk2(acc2[mi][0]);
        float2 u1 = upk2(acc2[mi][1]);
        float4 o;
        o.x = u0.x + bias4.x;
        o.y = u0.y + bias4.y;
        o.z = u1.x + bias4.z;
        o.w = u1.y + bias4.w;
        *(float4*)(Gout + ((size_t)(t * BSZ + b) << 11) + n) = o;
    }
}

// ---------------------------------------------------------------------------
// Kernel 2: persistent recurrence, v4 — batch-group pipelined barriers.
// 128 CTAs x 512 threads. CTA c: dir=c>>6, owns 8 hidden units (32 gate rows).
// Batch split into groups A=b0-15, B=b16-31, each with its OWN barrier.
// Each step: phase A then phase B; A's barrier wait is overlapped by B's
// compute of the previous step (recurrences are independent across batch).
// Warps 0-7 -> group-local b 0..7, warps 8-15 -> b 8..15; warp rq owns rows
// 4rq..4rq+3; lane owns swizzled 16-float k-chunk. f32x2 FMAs + 6-shfl fold.
// ---------------------------------------------------------------------------
__global__ void __launch_bounds__(512) rec_kernel(
    const float* __restrict__ Whh_f, const float* __restrict__ Whh_b,
    float* __restrict__ out, int out_size)
{
    __shared__ float hs[16 * HDIM];      // 32KB: one group's h
    __shared__ float gsm[2][32][17];     // [grp][row][b16] gate pre-activations
    __shared__ float csm[8][36];         // [jj][b32] cell state (padded)

    const int tid  = threadIdx.x;
    const int cta  = blockIdx.x;
    const int dir  = cta >> 6;
    const int cd   = cta & 63;
    const int j0   = cd * 8;
    const int lane = tid & 31;
    const int warp = tid >> 5;           // 0..15
    const int rq   = warp & 7;           // rows 4rq..4rq+3
    const int bh   = warp >> 3;          // group-local b half: 0..7 or 8..15
    const int q    = (lane >> 1) & 3;
    const int kbase = lane * 16;

    const float* __restrict__ Whh = dir ? Whh_b : Whh_f;

    int off[4];
    #pragma unroll
    for (int j = 0; j < 4; j++) off[j] = (j + q) & 3;

    // snapshot generation counters BEFORE any arrival (monotonic across launches;
    // gen can only bump after all 64 CTAs arrive, which is after every snapshot)
    unsigned gb0 = 0, gb1 = 0;
    if (tid == 0) {
        gb0 = *(volatile unsigned*)&g_gen[dir][0];
        gb1 = *(volatile unsigned*)&g_gen[dir][1];
    }

    // Load 4 rows x 16 k of Whh into packed u64 registers, swizzled k order
    unsigned long long w2[4][8];
    #pragma unroll
    for (int r = 0; r < 4; r++) {
        int r_local = 4 * rq + r;
        int gate = r_local >> 3;
        int jj   = r_local & 7;
        const ulonglong2* wrow =
            (const ulonglong2*)(Whh + (size_t)(gate * HDIM + j0 + jj) * HDIM + kbase);
        #pragma unroll
        for (int j = 0; j < 4; j++) {
            ulonglong2 wv = wrow[off[j]];
            w2[r][2 * j]     = wv.x;
            w2[r][2 * j + 1] = wv.y;
        }
    }

    // zero this direction's initial h (buf 0) + cell state
    if (tid < 256) (&g_h[0][dir][0][0])[cd * 256 + tid] = 0.0f;
    for (int i = tid; i < 8 * 36; i += 512) ((float*)csm)[i] = 0.0f;

    // preload step-0 input projections for both groups
    {
        const int t0 = dir ? (SEQ - 1) : 0;
        if (tid < 256) {
            int grp = tid >> 7;           // 0 or 1
            int lt  = tid & 127;
            int bb = lt >> 3;             // 0..15 group-local
            int r0 = (lt & 7) * 4;
            int gg = r0 >> 3;
            int j4 = r0 & 7;
            float4 gv = *(const float4*)&g_G[dir][t0][grp * 16 + bb][gg * HDIM + j0 + j4];
            gsm[grp][r0 + 0][bb] = gv.x; gsm[grp][r0 + 1][bb] = gv.y;
            gsm[grp][r0 + 2][bb] = gv.z; gsm[grp][r0 + 3][bb] = gv.w;
        }
    }

    __syncthreads();
    // init arrival on both group barriers (publishes zeroed h)
    if (tid == 0) {
        __threadfence();
        #pragma unroll
        for (int grp = 0; grp < 2; grp++) {
            unsigned gbase = grp ? gb1 : gb0;
            if (atomicAdd(&g_cnt[dir][grp], 1u) == 63u) {
                g_cnt[dir][grp] = 0u;
                __threadfence();
                g_gen[dir][grp] = gbase + 1u;
            }
        }
    }

    const bool write_tail = (out_size >= OUT_TOTAL);
    const int  r_red  = 4 * rq + ((lane >> 4) & 1) * 2 + ((lane >> 3) & 1);
    const bool writer = ((lane & 7) == 0);
    const bool hi16 = (lane & 16) != 0;
    const bool hi8  = (lane & 8)  != 0;

    for (int s = 0; s < SEQ; s++) {
        const int cur = s & 1, nxt = cur ^ 1;
        const int t = dir ? (SEQ - 1 - s) : s;

        #pragma unroll
        for (int grp = 0; grp < 2; grp++) {
            // ---- wait: h(s) for this group published by all CTAs ----
            if (tid == 0) {
                unsigned gbase = grp ? gb1 : gb0;
                unsigned target = gbase + 1u + (unsigned)s;
                volatile unsigned* genp = &g_gen[dir][grp];
                while ((int)(*genp - target) < 0) { }
                __threadfence();   // acquire (invalidates L1 for fresh h loads)
            }
            __syncthreads();

            // ---- stage this group's h[16][512] into smem (32KB) ----
            {
                const float4* src = (const float4*)&g_h[cur][dir][grp * 16][0];
                float4* dst = (float4*)hs;
                #pragma unroll
                for (int i = 0; i < 4; i++)
                    dst[tid + 512 * i] = src[tid + 512 * i];
            }
            __syncthreads();

            // ---- recurrent GEMM for this group ----
            const float* hrow = hs + kbase + bh * (8 * HDIM);
            #pragma unroll 2
            for (int bl = 0; bl < 8; bl++) {
                const ulonglong2* hp = (const ulonglong2*)(hrow + bl * HDIM);
                unsigned long long ha[8];
                #pragma unroll
                for (int j = 0; j < 4; j++) {
                    ulonglong2 hv = hp[off[j]];       // swizzled: conflict-free
                    ha[2 * j]     = hv.x;
                    ha[2 * j + 1] = hv.y;
                }
                unsigned long long a0 = 0, a1 = 0, a2 = 0, a3 = 0;
                #pragma unroll
                for (int j = 0; j < 8; j++) {
                    fma2(a0, ha[j], w2[0][j]);
                    fma2(a1, ha[j], w2[1][j]);
                    fma2(a2, ha[j], w2[2][j]);
                    fma2(a3, ha[j], w2[3][j]);
                }
                float s0 = red2(a0), s1 = red2(a1), s2 = red2(a2), s3 = red2(a3);
                float t0 = hi16 ? s0 : s2;
                float p0 = (hi16 ? s2 : s0) + __shfl_xor_sync(0xffffffffu, t0, 16);
                float t1 = hi16 ? s1 : s3;
                float p1 = (hi16 ? s3 : s1) + __shfl_xor_sync(0xffffffffu, t1, 16);
                float t2 = hi8 ? p0 : p1;
                float v  = (hi8 ? p1 : p0) + __shfl_xor_sync(0xffffffffu, t2, 8);
                v += __shfl_xor_sync(0xffffffffu, v, 4);
                v += __shfl_xor_sync(0xffffffffu, v, 2);
                v += __shfl_xor_sync(0xffffffffu, v, 1);
                if (writer) gsm[grp][r_red][bh * 8 + bl] += v;
            }
            __syncthreads();

            // ---- gates: thread -> (ej = tid&7, group-local eb = tid>>3) ----
            if (tid < 128) {
                const int ej = tid & 7;
                const int eb = tid >> 3;          // 0..15
                const int b  = grp * 16 + eb;
                float ig = gsm[grp][ej][eb];
                float fg = gsm[grp][8 + ej][eb];
                float gg = gsm[grp][16 + ej][eb];
                float og = gsm[grp][24 + ej][eb];
                float c = csm[ej][b];
                c = sigm(fg) * c + sigm(ig) * tanhf(gg);
                float h = sigm(og) * tanhf(c);
                csm[ej][b] = c;
                g_h[nxt][dir][b][j0 + ej] = h;
                out[(size_t)(b * SEQ + t) * (2 * HDIM) + dir * HDIM + j0 + ej] = h;
                if (s == SEQ - 1 && write_tail) {
                    out[OUT_HN_OFF + dir * (BSZ * HDIM) + b * HDIM + j0 + ej] = h;
                    out[OUT_CN_OFF + dir * (BSZ * HDIM) + b * HDIM + j0 + ej] = c;
                }
            }
            __syncthreads();

            // ---- arrive: publish h(s+1) for this group ----
            if (tid == 0) {
                unsigned gbase = grp ? gb1 : gb0;
                __threadfence();
                if (atomicAdd(&g_cnt[dir][grp], 1u) == 63u) {
                    g_cnt[dir][grp] = 0u;
                    __threadfence();
                    g_gen[dir][grp] = gbase + 2u + (unsigned)s;
                }
            }

            // ---- preload next step's G for this group (hidden under the
            //      other group's phase; gsm[grp] reads are past the sync) ----
            if (s + 1 < SEQ && tid < 128) {
                int tn = dir ? (SEQ - 2 - s) : (s + 1);
                int bb = tid >> 3;
                int r0 = (tid & 7) * 4;
                int gg = r0 >> 3;
                int j4 = r0 & 7;
                float4 gv = *(const float4*)&g_G[dir][tn][grp * 16 + bb][gg * HDIM + j0 + j4];
                gsm[grp][r0 + 0][bb] = gv.x; gsm[grp][r0 + 1][bb] = gv.y;
                gsm[grp][r0 + 2][bb] = gv.z; gsm[grp][r0 + 3][bb] = gv.w;
            }
        }
    }
}

extern "C" void kernel_launch(void* const* d_in, const int* in_sizes, int n_in,
                              void* d_out, int out_size) {
    const float* X     = (const float*)d_in[0];
    const float* Wih_f = (const float*)d_in[1];
    const float* Whh_f = (const float*)d_in[2];
    const float* bih_f = (const float*)d_in[3];
    const float* bhh_f = (const float*)d_in[4];
    const float* Wih_b = (const float*)d_in[5];
    const float* Whh_b = (const float*)d_in[6];
    const float* bih_b = (const float*)d_in[7];
    const float* bhh_b = (const float*)d_in[8];
    float* out = (float*)d_out;

    dim3 g1(G4H / 64, (BSZ * SEQ) / 64, 2);
    ih_gemm_kernel<<<g1, 256>>>(X, Wih_f, bih_f, bhh_f, Wih_b, bih_b, bhh_b);
    rec_kernel<<<128, 512>>>(Whh_f, Whh_b, out, out_size);
}

// round 6
// speedup vs baseline: 1.2246x; 1.2246x over previous
#include <cuda_runtime.h>
#include <math.h>

#define BSZ 32
#define SEQ 512
#define IDIM 512
#define HDIM 512
#define G4H 2048

#define OUT_HT_ELEMS (BSZ*SEQ*2*HDIM)              // 16777216
#define OUT_HN_OFF   OUT_HT_ELEMS
#define OUT_CN_OFF   (OUT_HT_ELEMS + 2*BSZ*HDIM)   // 16809984
#define OUT_TOTAL    (OUT_CN_OFF + 2*BSZ*HDIM)     // 16842752

// Scratch (allocation-free rule: __device__ globals)
__device__ float    g_G[2][SEQ][BSZ][G4H];   // precomputed x@Wih^T + bias, 256MB
__device__ float    g_h[2][2][BSZ][HDIM];    // [buf][dir][b][k] double-buffered h
__device__ unsigned g_cnt[2][2];             // [dir][half] arrival counters
__device__ unsigned g_gen[2][2];             // [dir][half] monotonic generation

__device__ __forceinline__ unsigned ld_acq(const unsigned* p) {
    unsigned v;
    asm volatile("ld.acquire.gpu.global.u32 %0, [%1];" : "=r"(v) : "l"(p));
    return v;
}
__device__ __forceinline__ unsigned atom_add_rel(unsigned* p, unsigned v) {
    unsigned old;
    asm volatile("atom.release.gpu.global.add.u32 %0, [%1], %2;"
                 : "=r"(old) : "l"(p), "r"(v));
    return old;
}
__device__ __forceinline__ void st_rel(unsigned* p, unsigned v) {
    asm volatile("st.release.gpu.global.u32 [%0], %1;" :: "l"(p), "r"(v));
}
__device__ __forceinline__ void half_bar(int id) {
    asm volatile("bar.sync %0, 256;" :: "r"(id));
}
__device__ __forceinline__ void fma2(unsigned long long& acc,
                                     unsigned long long a, unsigned long long b) {
    asm("fma.rn.f32x2 %0, %1, %2, %0;" : "+l"(acc) : "l"(a), "l"(b));
}
__device__ __forceinline__ float red2(unsigned long long v) {
    float lo, hi;
    asm("mov.b64 {%0, %1}, %2;" : "=f"(lo), "=f"(hi) : "l"(v));
    return lo + hi;
}
__device__ __forceinline__ unsigned long long dup2(float x) {
    unsigned long long r;
    asm("mov.b64 %0, {%1, %1};" : "=l"(r) : "f"(x));
    return r;
}
__device__ __forceinline__ float2 upk2(unsigned long long v) {
    float2 r;
    asm("mov.b64 {%0, %1}, %2;" : "=f"(r.x), "=f"(r.y) : "l"(v));
    return r;
}
__device__ __forceinline__ float sigm(float x) { return 1.0f / (1.0f + expf(-x)); }

// ---------------------------------------------------------------------------
// Kernel 1: input-projection GEMM with packed f32x2 FMAs (unchanged).
// ---------------------------------------------------------------------------
__global__ void __launch_bounds__(256) ih_gemm_kernel(
    const float* __restrict__ X,
    const float* __restrict__ Wih_f, const float* __restrict__ bih_f, const float* __restrict__ bhh_f,
    const float* __restrict__ Wih_b, const float* __restrict__ bih_b, const float* __restrict__ bhh_b)
{
    __shared__ float Xs[16][68];
    __shared__ float Ws[16][68];

    const int dir = blockIdx.z;
    const float* __restrict__ W   = dir ? Wih_b : Wih_f;
    const float* __restrict__ bih = dir ? bih_b : bih_f;
    const float* __restrict__ bhh = dir ? bhh_b : bhh_f;

    const int tid = threadIdx.x;
    const int tx = tid & 15;
    const int ty = tid >> 4;
    const int n0 = blockIdx.x * 64;
    const int m0 = blockIdx.y * 64;
    const int lrow = tid >> 2;
    const int lkq  = (tid & 3) * 4;

    unsigned long long acc2[4][2];
    #pragma unroll
    for (int i = 0; i < 4; i++) { acc2[i][0] = 0ull; acc2[i][1] = 0ull; }

    const float* Xp = X + (size_t)(m0 + lrow) * IDIM + lkq;
    const float* Wp = W + (size_t)(n0 + lrow) * IDIM + lkq;

    for (int k0 = 0; k0 < IDIM; k0 += 16) {
        float4 xv = *(const float4*)(Xp + k0);
        float4 wv = *(const float4*)(Wp + k0);
        Xs[lkq + 0][lrow] = xv.x; Xs[lkq + 1][lrow] = xv.y;
        Xs[lkq + 2][lrow] = xv.z; Xs[lkq + 3][lrow] = xv.w;
        Ws[lkq + 0][lrow] = wv.x; Ws[lkq + 1][lrow] = wv.y;
        Ws[lkq + 2][lrow] = wv.z; Ws[lkq + 3][lrow] = wv.w;
        __syncthreads();
        #pragma unroll
        for (int kk = 0; kk < 16; kk++) {
            float4 av = *(const float4*)&Xs[kk][ty * 4];
            ulonglong2 bp = *(const ulonglong2*)&Ws[kk][tx * 4];
            unsigned long long d0 = dup2(av.x);
            unsigned long long d1 = dup2(av.y);
            unsigned long long d2 = dup2(av.z);
            unsigned long long d3 = dup2(av.w);
            fma2(acc2[0][0], d0, bp.x); fma2(acc2[0][1], d0, bp.y);
            fma2(acc2[1][0], d1, bp.x); fma2(acc2[1][1], d1, bp.y);
            fma2(acc2[2][0], d2, bp.x); fma2(acc2[2][1], d2, bp.y);
            fma2(acc2[3][0], d3, bp.x); fma2(acc2[3][1], d3, bp.y);
        }
        __syncthreads();
    }

    const int n = n0 + tx * 4;
    float4 bias4;
    bias4.x = bih[n + 0] + bhh[n + 0];
    bias4.y = bih[n + 1] + bhh[n + 1];
    bias4.z = bih[n + 2] + bhh[n + 2];
    bias4.w = bih[n + 3] + bhh[n + 3];

    float* Gout = &g_G[dir][0][0][0];
    #pragma unroll
    for (int mi = 0; mi < 4; mi++) {
        int m = m0 + ty * 4 + mi;
        int b = m >> 9;
        int t = m & 511;
        float2 u0 = upk2(acc2[mi][0]);
        float2 u1 = upk2(acc2[mi][1]);
        float4 o;
        o.x = u0.x + bias4.x;
        o.y = u0.y + bias4.y;
        o.z = u1.x + bias4.z;
        o.w = u1.y + bias4.w;
        *(float4*)(Gout + ((size_t)(t * BSZ + b) << 11) + n) = o;
    }
}

// ---------------------------------------------------------------------------
// Kernel 2: persistent recurrence, v5 — CONCURRENT batch halves.
// 128 CTAs x 512 threads. CTA c: dir=c>>6, owns 8 hidden units (32 gate rows).
// Warps 0-7 process b0-15, warps 8-15 process b16-31 — as two fully
// independent pipelines with separate grid barriers g_gen[dir][half] and
// named CTA barriers (bar.sync 1+half, 256). When one half waits on its grid
// barrier, the other half's 8 warps keep the SM busy (SMT overlap).
// Sync is fence-free: ld.acquire.gpu polling + atom.release.gpu arrival;
// h traffic uses __ldcg/__stcg (L1 bypass -> L2-coherent, no CCTL needed).
// ---------------------------------------------------------------------------
__global__ void __launch_bounds__(512) rec_kernel(
    const float* __restrict__ Whh_f, const float* __restrict__ Whh_b,
    float* __restrict__ out, int out_size)
{
    __shared__ float hs[32 * HDIM];      // 64KB static: both halves' h
    __shared__ float gsm[32][33];        // [row][b] gate pre-activations
    __shared__ float csm[8][36];         // [jj][b] cell state (padded)
    __shared__ unsigned sbase[2];        // per-half gen snapshot

    const int tid  = threadIdx.x;
    const int cta  = blockIdx.x;
    const int dir  = cta >> 6;
    const int cd   = cta & 63;
    const int j0   = cd * 8;
    const int lane = tid & 31;
    const int warp = tid >> 5;           // 0..15
    const int rq   = warp & 7;           // rows 4rq..4rq+3
    const int bh   = warp >> 3;          // batch half (pipeline id)
    const int lt   = tid & 255;          // thread id within half
    const int barid = 1 + bh;
    const int q    = (lane >> 1) & 3;
    const int kbase = lane * 16;

    const float* __restrict__ Whh = dir ? Whh_b : Whh_f;

    int off[4];
    #pragma unroll
    for (int j = 0; j < 4; j++) off[j] = (j + q) & 3;

    // snapshot this half's generation BEFORE any arrival (quiescent between
    // launches since the stream serializes replays)
    if (lt == 0) sbase[bh] = *(volatile unsigned*)&g_gen[dir][bh];

    // Load 4 rows x 16 k of Whh into packed u64 registers, swizzled k order
    unsigned long long w2[4][8];
    #pragma unroll
    for (int r = 0; r < 4; r++) {
        int r_local = 4 * rq + r;
        int gate = r_local >> 3;
        int jj   = r_local & 7;
        const ulonglong2* wrow =
            (const ulonglong2*)(Whh + (size_t)(gate * HDIM + j0 + jj) * HDIM + kbase);
        #pragma unroll
        for (int j = 0; j < 4; j++) {
            ulonglong2 wv = wrow[off[j]];
            w2[r][2 * j]     = wv.x;
            w2[r][2 * j + 1] = wv.y;
        }
    }

    // zero this direction's initial h (buf 0) + cell state
    if (tid < 256) __stcg(&(&g_h[0][dir][0][0])[cd * 256 + tid], 0.0f);
    for (int i = tid; i < 8 * 36; i += 512) ((float*)csm)[i] = 0.0f;

    // preload step-0 input projection for this half
    if (lt < 128) {
        const int t0 = dir ? (SEQ - 1) : 0;
        int bb = bh * 16 + (lt >> 3);
        int r0 = (lt & 7) * 4;
        int gg = r0 >> 3;
        int j4 = r0 & 7;
        float4 gv = *(const float4*)&g_G[dir][t0][bb][gg * HDIM + j0 + j4];
        gsm[r0 + 0][bb] = gv.x; gsm[r0 + 1][bb] = gv.y;
        gsm[r0 + 2][bb] = gv.z; gsm[r0 + 3][bb] = gv.w;
    }

    __syncthreads();   // orders zero-init, csm, gsm, sbase for everyone
    const unsigned base = sbase[bh];

    // init arrival: publish zeroed h(0) for this half
    if (lt == 0) {
        if (atom_add_rel(&g_cnt[dir][bh], 1u) == 63u) {
            g_cnt[dir][bh] = 0u;
            st_rel(&g_gen[dir][bh], base + 1u);
        }
    }

    const bool write_tail = (out_size >= OUT_TOTAL);
    const int  r_red  = 4 * rq + ((lane >> 4) & 1) * 2 + ((lane >> 3) & 1);
    const bool writer = ((lane & 7) == 0);
    const bool hi16 = (lane & 16) != 0;
    const bool hi8  = (lane & 8)  != 0;

    for (int s = 0; s < SEQ; s++) {
        const int cur = s & 1, nxt = cur ^ 1;
        const int t = dir ? (SEQ - 1 - s) : s;

        // ---- wait: h(s) for this half published by all 64 CTAs ----
        {
            const unsigned target = base + 1u + (unsigned)s;
            while ((int)(ld_acq(&g_gen[dir][bh]) - target) < 0) { }
        }

        // ---- stage this half's h[16][512] into smem (L1-bypassing loads) ----
        {
            const float4* src = (const float4*)&g_h[cur][dir][bh * 16][0];
            float4* dst = (float4*)(hs + bh * 16 * HDIM);
            #pragma unroll
            for (int i = 0; i < 8; i++)
                dst[lt + 256 * i] = __ldcg(&src[lt + 256 * i]);
        }
        half_bar(barid);

        // ---- recurrent GEMM for this half's 16 batch rows ----
        const float* hrow = hs + kbase + bh * (16 * HDIM);
        #pragma unroll 2
        for (int bl = 0; bl < 16; bl++) {
            const int b = bh * 16 + bl;
            const ulonglong2* hp = (const ulonglong2*)(hrow + bl * HDIM);
            unsigned long long ha[8];
            #pragma unroll
            for (int j = 0; j < 4; j++) {
                ulonglong2 hv = hp[off[j]];       // swizzled: conflict-free
                ha[2 * j]     = hv.x;
                ha[2 * j + 1] = hv.y;
            }
            unsigned long long a0 = 0, a1 = 0, a2 = 0, a3 = 0;
            #pragma unroll
            for (int j = 0; j < 8; j++) {
                fma2(a0, ha[j], w2[0][j]);
                fma2(a1, ha[j], w2[1][j]);
                fma2(a2, ha[j], w2[2][j]);
                fma2(a3, ha[j], w2[3][j]);
            }
            float s0 = red2(a0), s1 = red2(a1), s2 = red2(a2), s3 = red2(a3);
            float t0 = hi16 ? s0 : s2;
            float p0 = (hi16 ? s2 : s0) + __shfl_xor_sync(0xffffffffu, t0, 16);
            float t1 = hi16 ? s1 : s3;
            float p1 = (hi16 ? s3 : s1) + __shfl_xor_sync(0xffffffffu, t1, 16);
            float t2 = hi8 ? p0 : p1;
            float v  = (hi8 ? p1 : p0) + __shfl_xor_sync(0xffffffffu, t2, 8);
            v += __shfl_xor_sync(0xffffffffu, v, 4);
            v += __shfl_xor_sync(0xffffffffu, v, 2);
            v += __shfl_xor_sync(0xffffffffu, v, 1);
            if (writer) gsm[r_red][b] += v;       // one writer per (row,b)
        }
        half_bar(barid);

        // ---- gates for this half: thread -> (ej, b) ----
        if (lt < 128) {
            const int ej = lt & 7;
            const int b  = bh * 16 + (lt >> 3);
            float ig = gsm[ej][b];
            float fg = gsm[8 + ej][b];
            float gg = gsm[16 + ej][b];
            float og = gsm[24 + ej][b];
            float c = csm[ej][b];
            c = sigm(fg) * c + sigm(ig) * tanhf(gg);
            float h = sigm(og) * tanhf(c);
            csm[ej][b] = c;
            __stcg(&g_h[nxt][dir][b][j0 + ej], h);
            out[(size_t)(b * SEQ + t) * (2 * HDIM) + dir * HDIM + j0 + ej] = h;
            if (s == SEQ - 1 && write_tail) {
                out[OUT_HN_OFF + dir * (BSZ * HDIM) + b * HDIM + j0 + ej] = h;
                out[OUT_CN_OFF + dir * (BSZ * HDIM) + b * HDIM + j0 + ej] = c;
            }
        }
        half_bar(barid);   // h stores + gsm reads done for this half

        // ---- arrive: publish h(s+1) for this half (release, cumulative
        //      over the half's stores via the preceding bar) ----
        if (lt == 0) {
            if (atom_add_rel(&g_cnt[dir][bh], 1u) == 63u) {
                g_cnt[dir][bh] = 0u;
                st_rel(&g_gen[dir][bh], base + 2u + (unsigned)s);
            }
        }

        // ---- preload next step's G for this half (no barrier needed:
        //      next compute's gsm access is after the post-stage bar) ----
        if (s + 1 < SEQ && lt < 128) {
            int tn = dir ? (SEQ - 2 - s) : (s + 1);
            int bb = bh * 16 + (lt >> 3);
            int r0 = (lt & 7) * 4;
            int gg = r0 >> 3;
            int j4 = r0 & 7;
            float4 gv = *(const float4*)&g_G[dir][tn][bb][gg * HDIM + j0 + j4];
            gsm[r0 + 0][bb] = gv.x; gsm[r0 + 1][bb] = gv.y;
            gsm[r0 + 2][bb] = gv.z; gsm[r0 + 3][bb] = gv.w;
        }
    }
}

extern "C" void kernel_launch(void* const* d_in, const int* in_sizes, int n_in,
                              void* d_out, int out_size) {
    const float* X     = (const float*)d_in[0];
    const float* Wih_f = (const float*)d_in[1];
    const float* Whh_f = (const float*)d_in[2];
    const float* bih_f = (const float*)d_in[3];
    const float* bhh_f = (const float*)d_in[4];
    const float* Wih_b = (const float*)d_in[5];
    const float* Whh_b = (const float*)d_in[6];
    const float* bih_b = (const float*)d_in[7];
    const float* bhh_b = (const float*)d_in[8];
    float* out = (float*)d_out;

    dim3 g1(G4H / 64, (BSZ * SEQ) / 64, 2);
    ih_gemm_kernel<<<g1, 256>>>(X, Wih_f, bih_f, bhh_f, Wih_b, bih_b, bhh_b);
    rec_kernel<<<128, 512>>>(Whh_f, Whh_b, out, out_size);
}